// round 10
// baseline (speedup 1.0000x reference)
#include <cuda_runtime.h>
#include <cuda_bf16.h>
#include <cstdint>

// HopfieldTSP: x_1000 = sign(w @ x0) (iterations 2..1000 are a provable fixed
// point; diagonal 2*rowsum dominates). One fused pass: rowsum_i + dot_i, sign.
//
// R10: R7's proven-correct TMA pipeline with the depth fixed. Model: chunk
// period = (sync + L_tma)/STAGES; R7 @4 stages -> 725cyc/chunk = 39% DRAM
// (matches measurement). 8 stages -> demand exceeds the 6300B/cyc LTS cap,
// so chip BW binds. 64KB dynamic smem ring, 3 blocks/SM = 192KB in flight/SM
// (vs ~32KB LDG MSHR ceiling that pinned all LDG variants at 5.7TB/s).

#define N_CITIES 8192
#define THREADS 256
#define ROWS_PER_BLOCK 16
#define NBLK (N_CITIES / ROWS_PER_BLOCK)      // 512
#define CHUNK_BYTES 8192
#define CHUNK_F4 (CHUNK_BYTES / 16)           // 512 float4
#define CHUNKS_PER_ROW 4                      // 32KB row / 8KB chunk
#define TOTAL_CHUNKS (ROWS_PER_BLOCK * CHUNKS_PER_ROW) // 64
#define STAGES 8
#define SMEM_DYN (STAGES * CHUNK_BYTES)       // 65536

__device__ __forceinline__ uint32_t smem_u32(const void* p) {
    uint32_t a;
    asm("{ .reg .u64 t; cvta.to.shared.u64 t, %1; cvt.u32.u64 %0, t; }"
        : "=r"(a) : "l"(p));
    return a;
}
__device__ __forceinline__ void mbar_init(uint32_t mbar, uint32_t cnt) {
    asm volatile("mbarrier.init.shared.b64 [%0], %1;" :: "r"(mbar), "r"(cnt) : "memory");
}
__device__ __forceinline__ void mbar_expect_tx(uint32_t mbar, uint32_t bytes) {
    asm volatile("mbarrier.arrive.expect_tx.shared.b64 _, [%0], %1;"
                 :: "r"(mbar), "r"(bytes) : "memory");
}
__device__ __forceinline__ void bulk_ld(uint32_t dst, const void* src,
                                        uint32_t bytes, uint32_t mbar) {
    asm volatile("cp.async.bulk.shared::cluster.global.mbarrier::complete_tx::bytes "
                 "[%0], [%1], %2, [%3];"
                 :: "r"(dst), "l"(src), "r"(bytes), "r"(mbar) : "memory");
}
__device__ __forceinline__ void mbar_wait(uint32_t mbar, uint32_t parity) {
    asm volatile(
        "{\n\t"
        ".reg .pred P;\n\t"
        "WL_%=:\n\t"
        "mbarrier.try_wait.parity.acquire.cta.shared::cta.b64 P, [%0], %1, 0x989680;\n\t"
        "@P bra.uni WD_%=;\n\t"
        "bra.uni WL_%=;\n\t"
        "WD_%=:\n\t"
        "}" :: "r"(mbar), "r"(parity) : "memory");
}

__global__ void __launch_bounds__(THREADS, 3)
hopfield_tma_kernel(const float* __restrict__ adj,
                    const float* __restrict__ x,
                    float* __restrict__ out) {
    extern __shared__ float4 buf[];                  // STAGES * 512 float4 = 64KB
    __shared__ alignas(8) uint64_t mbar_s[STAGES];
    __shared__ float red_rs[THREADS / 32], red_dot[THREADS / 32];

    const int tid  = threadIdx.x;
    const int warp = tid >> 5;
    const int lane = tid & 31;

    uint32_t mb[STAGES], bp[STAGES];
    #pragma unroll
    for (int s = 0; s < STAGES; s++) {
        mb[s] = smem_u32(&mbar_s[s]);
        bp[s] = smem_u32(&buf[(size_t)s * CHUNK_F4]);
    }

    if (tid == 0) {
        #pragma unroll
        for (int s = 0; s < STAGES; s++) mbar_init(mb[s], 1);
    }
    asm volatile("fence.proxy.async.shared::cta;" ::: "memory");
    __syncthreads();

    const int row0 = blockIdx.x * ROWS_PER_BLOCK;
    const char* src0 = reinterpret_cast<const char*>(adj)
                       + (size_t)row0 * N_CITIES * sizeof(float);

    // Prologue: fill all 8 stages (64KB in flight immediately).
    if (tid == 0) {
        #pragma unroll
        for (int c = 0; c < STAGES; c++) {
            mbar_expect_tx(mb[c], CHUNK_BYTES);
            bulk_ld(bp[c], src0 + (size_t)c * CHUNK_BYTES, CHUNK_BYTES, mb[c]);
        }
    }

    const float4* x4 = reinterpret_cast<const float4*>(x);
    float rs = 0.0f, dot = 0.0f;

    for (int c = 0; c < TOTAL_CHUNKS; c++) {
        const int stage  = c & (STAGES - 1);
        const int parity = (c >> 3) & 1;       // load # on this stage, mod 2
        mbar_wait(mb[stage], parity);

        const int k  = c & (CHUNKS_PER_ROW - 1);   // chunk within row
        const int xb = k * CHUNK_F4;
        float4 a0  = buf[stage * CHUNK_F4 + tid];
        float4 a1  = buf[stage * CHUNK_F4 + tid + THREADS];
        float4 xv0 = __ldg(&x4[xb + tid]);
        float4 xv1 = __ldg(&x4[xb + tid + THREADS]);
        rs  += (a0.x + a0.y) + (a0.z + a0.w) + (a1.x + a1.y) + (a1.z + a1.w);
        dot += a0.x * xv0.x + a0.y * xv0.y + a0.z * xv0.z + a0.w * xv0.w
             + a1.x * xv1.x + a1.y * xv1.y + a1.z * xv1.z + a1.w * xv1.w;

        __syncthreads();  // whole block done reading this stage (drain guarantee)
        if (tid == 0 && c + STAGES < TOTAL_CHUNKS) {
            mbar_expect_tx(mb[stage], CHUNK_BYTES);
            bulk_ld(bp[stage], src0 + (size_t)(c + STAGES) * CHUNK_BYTES,
                    CHUNK_BYTES, mb[stage]);
        }

        if (k == CHUNKS_PER_ROW - 1) {
            // End of row: block reduction of (rs, dot).
            #pragma unroll
            for (int o = 16; o > 0; o >>= 1) {
                rs  += __shfl_xor_sync(0xFFFFFFFFu, rs, o);
                dot += __shfl_xor_sync(0xFFFFFFFFu, dot, o);
            }
            if (lane == 0) { red_rs[warp] = rs; red_dot[warp] = dot; }
            __syncthreads();
            if (warp == 0 && lane < THREADS / 32) {
                float r = red_rs[lane], d = red_dot[lane];
                #pragma unroll
                for (int o = 4; o > 0; o >>= 1) {
                    r += __shfl_xor_sync(0xFFu, r, o);
                    d += __shfl_xor_sync(0xFFu, d, o);
                }
                if (lane == 0) {
                    const int row = row0 + (c >> 2);
                    float aii = __ldg(adj + (size_t)row * N_CITIES + row);
                    float xi  = __ldg(x + row);
                    float s   = (2.0f * r + aii) * xi - d;
                    out[row] = (s > 0.0f) ? 1.0f : ((s < 0.0f) ? -1.0f : 0.0f);
                }
            }
            rs = 0.0f;
            dot = 0.0f;
        }
    }
}

extern "C" void kernel_launch(void* const* d_in, const int* in_sizes, int n_in,
                              void* d_out, int out_size) {
    const float* adj = (const float*)d_in[0];   // [8192, 8192] fp32 row-major
    const float* x   = (const float*)d_in[1];   // [8192] fp32
    float* out       = (float*)d_out;           // [8192] fp32

    cudaFuncSetAttribute(hopfield_tma_kernel,
                         cudaFuncAttributeMaxDynamicSharedMemorySize, SMEM_DYN);
    hopfield_tma_kernel<<<NBLK, THREADS, SMEM_DYN>>>(adj, x, out);
}

// round 11
// speedup vs baseline: 1.5860x; 1.5860x over previous
#include <cuda_runtime.h>
#include <cuda_bf16.h>
#include <cstdint>

// HopfieldTSP: x_1000 = sign(w @ x0) (iterations 2..1000 are a provable fixed
// point; diagonal 2*rowsum dominates). One fused pass: rowsum_i + dot_i, sign.
//
// R11: TMA branch closed (2 structural failures). Back to the proven R5 shape
// with the ONE untried streaming mechanism: cp.async (LDGSTS) — per-thread
// 8-deep ring into smem, commit-group per iteration, wait_group 7. Tracking
// is per-thread group-based ("depth cap NONE" per B300 measurements), giving
// ~131KB in flight/SM vs the ~32KB LDG ceiling that pinned every LDG variant
// at 5.7TB/s. Thread-private slots -> zero barriers in the stream.

#define N_CITIES 8192
#define THREADS 256
#define WARPS 8
#define ROWS_PER_BLOCK 8
#define ROW4 (N_CITIES / 4)     // 2048 float4 per row
#define NITER (ROW4 / 32)       // 64 iterations per lane
#define D 8                     // pipeline depth (stages per thread)

__device__ __forceinline__ uint32_t smem_u32(const void* p) {
    uint32_t a;
    asm("{ .reg .u64 t; cvta.to.shared.u64 t, %1; cvt.u32.u64 %0, t; }"
        : "=r"(a) : "l"(p));
    return a;
}
__device__ __forceinline__ void cp16(uint32_t dst, const void* src) {
    asm volatile("cp.async.cg.shared.global [%0], [%1], 16;"
                 :: "r"(dst), "l"(src) : "memory");
}
__device__ __forceinline__ void cp_commit() {
    asm volatile("cp.async.commit_group;" ::: "memory");
}
__device__ __forceinline__ void cp_wait7() {
    asm volatile("cp.async.wait_group 7;" ::: "memory");
}

__global__ void __launch_bounds__(THREADS, 4)
hopfield_cpasync_kernel(const float* __restrict__ adj,
                        const float* __restrict__ x,
                        float* __restrict__ out) {
    // [warp][stage][lane] float4 — each thread owns slots [warp][*][lane].
    __shared__ float4 stg[WARPS][D][32];   // 32 KB

    const int warp = threadIdx.x >> 5;
    const int lane = threadIdx.x & 31;
    const int row  = blockIdx.x * ROWS_PER_BLOCK + warp;

    const float4* arow = reinterpret_cast<const float4*>(adj + (size_t)row * N_CITIES);
    const float4* x4   = reinterpret_cast<const float4*>(x);

    // Thread's stage-s slot address; stage stride = 32 float4 = 512 B.
    const uint32_t sbase = smem_u32(&stg[warp][0][lane]);

    // Prologue: fill all D stages (one commit group per stage).
    #pragma unroll
    for (int s = 0; s < D; s++) {
        cp16(sbase + s * 512, arow + lane + 32 * s);
        cp_commit();
    }

    float rs = 0.0f, dot = 0.0f;
    #pragma unroll 8
    for (int k = 0; k < NITER; k++) {
        // Invariant: k+D groups committed so far -> wait_group 7 guarantees
        // group k (chunk k) is complete and visible.
        cp_wait7();
        float4 a  = stg[warp][k & (D - 1)][lane];
        // Refill this slot with chunk k+D (or commit an empty group at tail
        // to preserve the group<->iteration invariant).
        if (k + D < NITER) cp16(sbase + (k & (D - 1)) * 512, arow + lane + 32 * (k + D));
        cp_commit();

        float4 xv = __ldg(&x4[lane + 32 * k]);
        rs  += (a.x + a.y) + (a.z + a.w);
        dot += a.x * xv.x + a.y * xv.y + a.z * xv.z + a.w * xv.w;
    }

    #pragma unroll
    for (int o = 16; o > 0; o >>= 1) {
        rs  += __shfl_xor_sync(0xFFFFFFFFu, rs, o);
        dot += __shfl_xor_sync(0xFFFFFFFFu, dot, o);
    }

    if (lane == 0) {
        float aii = __ldg(adj + (size_t)row * N_CITIES + row);
        float xi  = __ldg(x + row);
        float s   = (2.0f * rs + aii) * xi - dot;
        out[row] = (s > 0.0f) ? 1.0f : ((s < 0.0f) ? -1.0f : 0.0f);
    }
}

extern "C" void kernel_launch(void* const* d_in, const int* in_sizes, int n_in,
                              void* d_out, int out_size) {
    const float* adj = (const float*)d_in[0];   // [8192, 8192] fp32 row-major
    const float* x   = (const float*)d_in[1];   // [8192] fp32
    float* out       = (float*)d_out;           // [8192] fp32

    hopfield_cpasync_kernel<<<N_CITIES / ROWS_PER_BLOCK, THREADS>>>(adj, x, out);
}

// round 12
// speedup vs baseline: 1.6514x; 1.0412x over previous
#include <cuda_runtime.h>
#include <cuda_bf16.h>

// HopfieldTSP: x_1000 = sign(w @ x0). Iterations 2..1000 are a provable fixed
// point (diagonal 2*rowsum_i ~ 8192 dominates |sum_j adj_ij*(+-1)| <= rowsum_i),
// so ONE fused pass over adj computes rowsum_i and dot_i = (adj@x0)_i, then
//   s_i = (2*rowsum_i + adj_ii)*x0_i - dot_i ;  out_i = sign(s_i).
//
// R12 (final): the ~5.7TB/s read plateau was reproduced across LDG (all four
// cache-ops), TMA bulk pipelines, and cp.async with 118KB/SM in flight — it is
// the chip's effective read ceiling for this pattern at NAT clocks, not an
// SM-side limit. Final config combines the best-measured ingredients:
// 256-thread blocks, one full row per warp (no barriers, no staging sync),
// default cache-op (best: 47.2us), unroll 4 (best), x via __ldg hot in L1,
// grid 1024 = single wave at 8 blocks/SM.

#define N_CITIES 8192
#define THREADS 256
#define ROWS_PER_BLOCK (THREADS / 32)   // 8
#define ROW4 (N_CITIES / 4)             // 2048 float4 per row

__global__ void __launch_bounds__(THREADS, 8)
hopfield_fused_kernel(const float* __restrict__ adj,
                      const float* __restrict__ x,
                      float* __restrict__ out) {
    const int warp = threadIdx.x >> 5;
    const int lane = threadIdx.x & 31;
    const int row  = blockIdx.x * ROWS_PER_BLOCK + warp;

    const float4* arow = reinterpret_cast<const float4*>(adj + (size_t)row * N_CITIES);
    const float4* x4   = reinterpret_cast<const float4*>(x);

    // 64 trips per lane; default cache-op (best measured), unroll 4.
    float rs = 0.0f, dot = 0.0f;
    #pragma unroll 4
    for (int j = lane; j < ROW4; j += 32) {
        float4 a  = arow[j];
        float4 xv = __ldg(&x4[j]);
        rs  += (a.x + a.y) + (a.z + a.w);
        dot += a.x * xv.x + a.y * xv.y + a.z * xv.z + a.w * xv.w;
    }

    #pragma unroll
    for (int o = 16; o > 0; o >>= 1) {
        rs  += __shfl_xor_sync(0xFFFFFFFFu, rs, o);
        dot += __shfl_xor_sync(0xFFFFFFFFu, dot, o);
    }

    if (lane == 0) {
        float aii = __ldg(adj + (size_t)row * N_CITIES + row);
        float xi  = __ldg(x + row);
        float s   = (2.0f * rs + aii) * xi - dot;
        out[row] = (s > 0.0f) ? 1.0f : ((s < 0.0f) ? -1.0f : 0.0f);
    }
}

extern "C" void kernel_launch(void* const* d_in, const int* in_sizes, int n_in,
                              void* d_out, int out_size) {
    const float* adj = (const float*)d_in[0];   // [8192, 8192] fp32 row-major
    const float* x   = (const float*)d_in[1];   // [8192] fp32
    float* out       = (float*)d_out;           // [8192] fp32

    hopfield_fused_kernel<<<N_CITIES / ROWS_PER_BLOCK, THREADS>>>(adj, x, out);
}